// round 10
// baseline (speedup 1.0000x reference)
#include <cuda_runtime.h>
#include <cuda_fp16.h>
#include <math.h>

#define NN    150000
#define DIMN  64
#define NE    1200000
#define NRELN 32
#define NLAY  2
#define SLOTS 64
#define GROW  ((NN + 127) / 128)

// ---------------- scratch (device globals; no allocation allowed) ----------------
__device__ __half g_xth[NN * DIMN];     // xt = x @ W, fp16 (gather operand, 128B/row)
__device__ float  g_x[NN * DIMN];       // layer input x (post-epilogue), fp32
__device__ float  g_ssrc[NN];           // xt @ a_src
__device__ float  g_sdst[NN];           // xt @ a_dst
__device__ float  g_srel[NLAY * NRELN]; // rel @ (W_r @ a_rel), both layers
__device__ int    g_cnt[NN];            // per-dst degree
__device__ int    g_slot[NN * SLOTS];   // per-dst packed (src | etype<<18)

// ---------------- packed f32x2 helpers ----------------
__device__ __forceinline__ unsigned long long pack2(float lo, float hi) {
    unsigned long long r;
    asm("mov.b64 %0, {%1,%2};" : "=l"(r) : "f"(lo), "f"(hi));
    return r;
}
__device__ __forceinline__ void ffma2(unsigned long long& d,
                                      unsigned long long a, unsigned long long b) {
    asm("fma.rn.f32x2 %0, %1, %2, %3;" : "=l"(d) : "l"(a), "l"(b), "l"(d));
}
__device__ __forceinline__ float sum2(unsigned long long v) {
    unsigned int lo, hi;
    asm("mov.b64 {%0,%1}, %2;" : "=r"(lo), "=r"(hi) : "l"(v));
    return __uint_as_float(lo) + __uint_as_float(hi);
}
__device__ __forceinline__ unsigned int h2_from_acc2(unsigned long long v) {
    unsigned int lo, hi;
    asm("mov.b64 {%0,%1}, %2;" : "=r"(lo), "=r"(hi) : "l"(v));
    __half2 h = __floats2half2_rn(__uint_as_float(lo), __uint_as_float(hi));
    return *(unsigned int*)&h;
}

// row GEMM: xt[row] = xv @ Ws  (+ s_src/s_dst epilogue).  Packed f32x2 FMA.
// Writes xt in fp16 (one 128B line per row).
__device__ __forceinline__ void gemm_row(const float4* xv, const float* Ws,
                                         const float* a_s, const float* a_d, int row) {
    unsigned long long acc2[32];
#pragma unroll
    for (int p = 0; p < 32; p++) acc2[p] = 0ull;

#pragma unroll 2
    for (int kk = 0; kk < 16; kk++) {
        float4 x4 = xv[kk];
#pragma unroll
        for (int q = 0; q < 4; q++) {
            float xk = (q == 0) ? x4.x : (q == 1) ? x4.y : (q == 2) ? x4.z : x4.w;
            unsigned long long xx = pack2(xk, xk);
            const ulonglong2* Wr = (const ulonglong2*)(Ws + (4 * kk + q) * DIMN);
#pragma unroll
            for (int p2 = 0; p2 < 16; p2++) {
                ulonglong2 w2 = Wr[p2];
                ffma2(acc2[2 * p2 + 0], xx, w2.x);
                ffma2(acc2[2 * p2 + 1], xx, w2.y);
            }
        }
    }

    unsigned long long ss2 = 0ull, sd2 = 0ull;
    const unsigned long long* as_p = (const unsigned long long*)a_s;
    const unsigned long long* ad_p = (const unsigned long long*)a_d;
#pragma unroll
    for (int p = 0; p < 32; p++) {
        ffma2(ss2, acc2[p], as_p[p]);
        ffma2(sd2, acc2[p], ad_p[p]);
    }
    g_ssrc[row] = sum2(ss2);
    g_sdst[row] = sum2(sd2);

    uint4* op = (uint4*)(g_xth + (size_t)row * DIMN);
#pragma unroll
    for (int i = 0; i < 8; i++) {
        uint4 st;
        st.x = h2_from_acc2(acc2[4 * i + 0]);
        st.y = h2_from_acc2(acc2[4 * i + 1]);
        st.z = h2_from_acc2(acc2[4 * i + 2]);
        st.w = h2_from_acc2(acc2[4 * i + 3]);
        op[i] = st;
    }
}

// ---------------- bucket build ----------------
__global__ void kZero() {
    int i = blockIdx.x * blockDim.x + threadIdx.x;
    if (i < NN) g_cnt[i] = 0;
}

__global__ void kFill(const int* __restrict__ src, const int* __restrict__ dst,
                      const int* __restrict__ et) {
    int i = blockIdx.x * blockDim.x + threadIdx.x;
    if (i >= NE) return;
    int d = dst[i];
    int pos = atomicAdd(&g_cnt[d], 1);
    if (pos < SLOTS) g_slot[d * SLOTS + pos] = src[i] | (et[i] << 18);
}

// ---------------- GEMM + score kernels ----------------
// layer 0: also acc = node_emb, and 2 tail blocks compute srel for both layers
__global__ __launch_bounds__(128)
void kG0(const float* __restrict__ node_emb, const float* __restrict__ W,
         const float* __restrict__ a, const float* __restrict__ W_r,
         const float* __restrict__ rel, float* __restrict__ acc) {
    __shared__ float Ws[DIMN * DIMN];
    __shared__ float a_s[DIMN], a_d[DIMN];
    __shared__ float v[DIMN];

    if (blockIdx.x >= GROW) {                 // srel tail blocks (layer 0/1)
        int l = blockIdx.x - GROW;
        int t = threadIdx.x;
        const float* Wr = W_r + (size_t)l * DIMN * DIMN;
        const float* ar = a + (size_t)l * 3 * DIMN + DIMN;
        if (t < DIMN) {
            float s = 0.f;
#pragma unroll
            for (int j = 0; j < DIMN; j++) s += Wr[t * DIMN + j] * ar[j];
            v[t] = s;
        }
        __syncthreads();
        if (t < NRELN) {
            const float* rl = rel + (size_t)l * NRELN * DIMN + (size_t)t * DIMN;
            float r = 0.f;
#pragma unroll
            for (int k = 0; k < DIMN; k++) r += rl[k] * v[k];
            g_srel[l * NRELN + t] = r;
        }
        return;
    }

    for (int i = threadIdx.x; i < DIMN * DIMN; i += 128) Ws[i] = W[i];
    if (threadIdx.x < DIMN) {
        a_s[threadIdx.x] = a[threadIdx.x];
        a_d[threadIdx.x] = a[2 * DIMN + threadIdx.x];
    }
    __syncthreads();

    int row = blockIdx.x * 128 + threadIdx.x;
    if (row >= NN) return;

    float4 xv[16];
    const float4* xp = (const float4*)(node_emb + (size_t)row * DIMN);
    float4* ap = (float4*)(acc + (size_t)row * DIMN);
#pragma unroll
    for (int j = 0; j < 16; j++) { xv[j] = xp[j]; ap[j] = xv[j]; }

    gemm_row(xv, Ws, a_s, a_d, row);
}

// layer 1: x from g_x
__global__ __launch_bounds__(128)
void kG1(const float* __restrict__ W, const float* __restrict__ a) {
    __shared__ float Ws[DIMN * DIMN];
    __shared__ float a_s[DIMN], a_d[DIMN];
    for (int i = threadIdx.x; i < DIMN * DIMN; i += 128) Ws[i] = W[i];
    if (threadIdx.x < DIMN) {
        a_s[threadIdx.x] = a[threadIdx.x];
        a_d[threadIdx.x] = a[2 * DIMN + threadIdx.x];
    }
    __syncthreads();

    int row = blockIdx.x * 128 + threadIdx.x;
    if (row >= NN) return;

    float4 xv[16];
    const float4* xp = (const float4*)(g_x + (size_t)row * DIMN);
#pragma unroll
    for (int j = 0; j < 16; j++) xv[j] = xp[j];

    gemm_row(xv, Ws, a_s, a_d, row);
}

// ---------------- gather aggregation: one warp per dst node ----------------
// Stage 2: FOUR edges per warp trip. Quarter-warp (8 lanes) per edge, each
// lane loads one uint4 (16B = 8 fp16 cols); one 128B line per edge. Quarters
// combined by shfl_xor(8) + shfl_xor(16). Staging packed as uint2 {w, rowbase}.
__global__ __launch_bounds__(256)
void kAgg(float* __restrict__ acc, int layer, int is_final) {
    __shared__ uint2 sh[8][SLOTS];

    int wid  = threadIdx.x >> 5;
    int lane = threadIdx.x & 31;
    int n = blockIdx.x * 8 + wid;           // grid sized exactly: 18750*8 = NN

    int deg = g_cnt[n];
    deg = (deg > SLOTS) ? SLOTS : deg;
    float sdst_n = g_sdst[n];
    const float* srel_l = g_srel + layer * NRELN;
    const int* slot = g_slot + n * SLOTS;

    // stage 1: lane-parallel edge weights (MLP on random score loads)
    float att = 0.f;
    for (int j = lane; j < deg; j += 32) {
        int p = slot[j];
        int s = p & 0x3FFFF;
        int et = p >> 18;
        float e = g_ssrc[s] + srel_l[et] + sdst_n;
        e = (e > 0.f) ? e : 0.2f * e;
        float w = __expf(e);
        sh[wid][j] = make_uint2(__float_as_uint(w), (unsigned)s * 8u);  // row base in uint4 units
        att += w;
    }
#pragma unroll
    for (int o = 16; o > 0; o >>= 1) att += __shfl_xor_sync(0xffffffffu, att, o);
    __syncwarp();

    // stage 2: 4 edges per trip; quarter-warp owns one edge's 8 uint4 chunks
    int q  = lane >> 3;                     // which of 4 concurrent edges
    int c8 = lane & 7;                      // uint4 chunk (cols 8*c8 .. 8*c8+7)
    float4 h0 = make_float4(0.f, 0.f, 0.f, 0.f);
    float4 h1 = make_float4(0.f, 0.f, 0.f, 0.f);
    const uint4* xh = (const uint4*)g_xth;
#pragma unroll 2
    for (int j = q; j < deg; j += 4) {
        uint2 t = sh[wid][j];
        float w = __uint_as_float(t.x);
        uint4 u = __ldg(&xh[t.y + c8]);
        float2 a0 = __half22float2(*(const __half2*)&u.x);
        float2 a1 = __half22float2(*(const __half2*)&u.y);
        float2 a2 = __half22float2(*(const __half2*)&u.z);
        float2 a3 = __half22float2(*(const __half2*)&u.w);
        h0.x += w * a0.x; h0.y += w * a0.y; h0.z += w * a1.x; h0.w += w * a1.y;
        h1.x += w * a2.x; h1.y += w * a2.y; h1.z += w * a3.x; h1.w += w * a3.y;
    }
    // combine the four quarters (lanes sharing c8 hold the same columns)
#pragma unroll
    for (int o = 8; o <= 16; o <<= 1) {
        h0.x += __shfl_xor_sync(0xffffffffu, h0.x, o);
        h0.y += __shfl_xor_sync(0xffffffffu, h0.y, o);
        h0.z += __shfl_xor_sync(0xffffffffu, h0.z, o);
        h0.w += __shfl_xor_sync(0xffffffffu, h0.w, o);
        h1.x += __shfl_xor_sync(0xffffffffu, h1.x, o);
        h1.y += __shfl_xor_sync(0xffffffffu, h1.y, o);
        h1.z += __shfl_xor_sync(0xffffffffu, h1.z, o);
        h1.w += __shfl_xor_sync(0xffffffffu, h1.w, o);
    }

    float inv_s = 1.f / (att + 1e-10f);
    h0.x *= inv_s; h0.y *= inv_s; h0.z *= inv_s; h0.w *= inv_s;
    h1.x *= inv_s; h1.y *= inv_s; h1.z *= inv_s; h1.w *= inv_s;
    h0.x = (h0.x > 0.f) ? h0.x : __expf(h0.x) - 1.f;   // ELU
    h0.y = (h0.y > 0.f) ? h0.y : __expf(h0.y) - 1.f;
    h0.z = (h0.z > 0.f) ? h0.z : __expf(h0.z) - 1.f;
    h0.w = (h0.w > 0.f) ? h0.w : __expf(h0.w) - 1.f;
    h1.x = (h1.x > 0.f) ? h1.x : __expf(h1.x) - 1.f;
    h1.y = (h1.y > 0.f) ? h1.y : __expf(h1.y) - 1.f;
    h1.z = (h1.z > 0.f) ? h1.z : __expf(h1.z) - 1.f;
    h1.w = (h1.w > 0.f) ? h1.w : __expf(h1.w) - 1.f;

    float ss = h0.x * h0.x + h0.y * h0.y + h0.z * h0.z + h0.w * h0.w
             + h1.x * h1.x + h1.y * h1.y + h1.z * h1.z + h1.w * h1.w;
#pragma unroll
    for (int o = 4; o > 0; o >>= 1) ss += __shfl_xor_sync(0xffffffffu, ss, o);
    float inv = 1.f / fmaxf(sqrtf(ss), 1e-12f);
    h0.x *= inv; h0.y *= inv; h0.z *= inv; h0.w *= inv;
    h1.x *= inv; h1.y *= inv; h1.z *= inv; h1.w *= inv;

    if (q == 0) {                           // lanes 0-7 write the row (2 float4 each)
        float4* ap = (float4*)(acc + n * DIMN) + 2 * c8;
        float4 a0 = ap[0], a1 = ap[1];
        if (is_final) {
            const float fs = 1.f / (float)(NLAY + 1);
            a0.x = (a0.x + h0.x) * fs; a0.y = (a0.y + h0.y) * fs;
            a0.z = (a0.z + h0.z) * fs; a0.w = (a0.w + h0.w) * fs;
            a1.x = (a1.x + h1.x) * fs; a1.y = (a1.y + h1.y) * fs;
            a1.z = (a1.z + h1.z) * fs; a1.w = (a1.w + h1.w) * fs;
            ap[0] = a0; ap[1] = a1;
        } else {
            a0.x += h0.x; a0.y += h0.y; a0.z += h0.z; a0.w += h0.w;
            a1.x += h1.x; a1.y += h1.y; a1.z += h1.z; a1.w += h1.w;
            ap[0] = a0; ap[1] = a1;
            float4* xp = (float4*)(g_x + n * DIMN) + 2 * c8;
            xp[0] = h0; xp[1] = h1;
        }
    }
}

// ---------------- launch: fork bucket-build onto a side stream ----------------
extern "C" void kernel_launch(void* const* d_in, const int* in_sizes, int n_in,
                              void* d_out, int out_size) {
    const float* node_emb = (const float*)d_in[0];
    const float* W        = (const float*)d_in[1];   // [2,64,64]
    const float* W_r      = (const float*)d_in[2];   // [2,64,64]
    const float* a        = (const float*)d_in[3];   // [2,192]
    const float* rel      = (const float*)d_in[4];   // [2,32,64]
    const int*   eidx     = (const int*)d_in[5];     // [2, NE]
    const int*   etype    = (const int*)d_in[6];     // [NE]
    const int* src = eidx;
    const int* dst = eidx + NE;
    float* out = (float*)d_out;

    cudaStream_t side;
    cudaEvent_t eFork, eJoin;
    bool forked = (cudaStreamCreateWithFlags(&side, cudaStreamNonBlocking) == cudaSuccess) &&
                  (cudaEventCreateWithFlags(&eFork, cudaEventDisableTiming) == cudaSuccess) &&
                  (cudaEventCreateWithFlags(&eJoin, cudaEventDisableTiming) == cudaSuccess);

    if (forked) {
        // branch A (side): bucket build.  branch B (main): GEMM + scores.
        cudaEventRecord(eFork, 0);
        cudaStreamWaitEvent(side, eFork, 0);
        kZero<<<(NN + 255) / 256, 256, 0, side>>>();
        kFill<<<(NE + 255) / 256, 256, 0, side>>>(src, dst, etype);
        cudaEventRecord(eJoin, side);

        kG0<<<GROW + 2, 128>>>(node_emb, W, a, W_r, rel, out);
        cudaStreamWaitEvent(0, eJoin, 0);
    } else {
        kZero<<<(NN + 255) / 256, 256>>>();
        kFill<<<(NE + 255) / 256, 256>>>(src, dst, etype);
        kG0<<<GROW + 2, 128>>>(node_emb, W, a, W_r, rel, out);
    }

    kAgg<<<NN / 8, 256>>>(out, 0, 0);
    kG1<<<GROW, 128>>>(W + DIMN * DIMN, a + 3 * DIMN);
    kAgg<<<NN / 8, 256>>>(out, 1, 1);
    // streams/events intentionally not destroyed: kernel_launch is invoked only
    // a handful of times (correctness + capture); graph replay re-executes the
    // captured GPU work, not this host code.
}

// round 12
// speedup vs baseline: 1.2588x; 1.2588x over previous
#include <cuda_runtime.h>
#include <cuda_fp16.h>
#include <math.h>

#define NN    150000
#define DIMN  64
#define NE    1200000
#define NRELN 32
#define NLAY  2
#define SLOTS 64
#define GROW  ((NN + 127) / 128)

// ---------------- scratch (device globals; no allocation allowed) ----------------
__device__ __half g_xth[NN * DIMN];     // xt = x @ W, fp16 (gather operand, 128B/row)
__device__ float  g_x[NN * DIMN];       // layer input x (post-epilogue), fp32
__device__ float  g_ssrc[NN];           // xt @ a_src
__device__ float  g_sdst[NN];           // xt @ a_dst
__device__ float  g_srel[NLAY * NRELN]; // rel @ (W_r @ a_rel), both layers
__device__ int    g_cnt[NN];            // per-dst degree (zero-init at load; kAgg-final re-zeroes)
__device__ int    g_slot[NN * SLOTS];   // per-dst packed (src | etype<<18)

// ---------------- packed f32x2 helpers ----------------
__device__ __forceinline__ unsigned long long pack2(float lo, float hi) {
    unsigned long long r;
    asm("mov.b64 %0, {%1,%2};" : "=l"(r) : "f"(lo), "f"(hi));
    return r;
}
__device__ __forceinline__ void ffma2(unsigned long long& d,
                                      unsigned long long a, unsigned long long b) {
    asm("fma.rn.f32x2 %0, %1, %2, %3;" : "=l"(d) : "l"(a), "l"(b), "l"(d));
}
__device__ __forceinline__ float sum2(unsigned long long v) {
    unsigned int lo, hi;
    asm("mov.b64 {%0,%1}, %2;" : "=r"(lo), "=r"(hi) : "l"(v));
    return __uint_as_float(lo) + __uint_as_float(hi);
}
__device__ __forceinline__ unsigned int h2_from_acc2(unsigned long long v) {
    unsigned int lo, hi;
    asm("mov.b64 {%0,%1}, %2;" : "=r"(lo), "=r"(hi) : "l"(v));
    __half2 h = __floats2half2_rn(__uint_as_float(lo), __uint_as_float(hi));
    return *(unsigned int*)&h;
}

// row GEMM: xt[row] = xv @ Ws  (+ s_src/s_dst epilogue).  Packed f32x2 FMA.
// Writes xt in fp16 (one 128B line per row).
__device__ __forceinline__ void gemm_row(const float4* xv, const float* Ws,
                                         const float* a_s, const float* a_d, int row) {
    unsigned long long acc2[32];
#pragma unroll
    for (int p = 0; p < 32; p++) acc2[p] = 0ull;

#pragma unroll 2
    for (int kk = 0; kk < 16; kk++) {
        float4 x4 = xv[kk];
#pragma unroll
        for (int q = 0; q < 4; q++) {
            float xk = (q == 0) ? x4.x : (q == 1) ? x4.y : (q == 2) ? x4.z : x4.w;
            unsigned long long xx = pack2(xk, xk);
            const ulonglong2* Wr = (const ulonglong2*)(Ws + (4 * kk + q) * DIMN);
#pragma unroll
            for (int p2 = 0; p2 < 16; p2++) {
                ulonglong2 w2 = Wr[p2];
                ffma2(acc2[2 * p2 + 0], xx, w2.x);
                ffma2(acc2[2 * p2 + 1], xx, w2.y);
            }
        }
    }

    unsigned long long ss2 = 0ull, sd2 = 0ull;
    const unsigned long long* as_p = (const unsigned long long*)a_s;
    const unsigned long long* ad_p = (const unsigned long long*)a_d;
#pragma unroll
    for (int p = 0; p < 32; p++) {
        ffma2(ss2, acc2[p], as_p[p]);
        ffma2(sd2, acc2[p], ad_p[p]);
    }
    g_ssrc[row] = sum2(ss2);
    g_sdst[row] = sum2(sd2);

    uint4* op = (uint4*)(g_xth + (size_t)row * DIMN);
#pragma unroll
    for (int i = 0; i < 8; i++) {
        uint4 st;
        st.x = h2_from_acc2(acc2[4 * i + 0]);
        st.y = h2_from_acc2(acc2[4 * i + 1]);
        st.z = h2_from_acc2(acc2[4 * i + 2]);
        st.w = h2_from_acc2(acc2[4 * i + 3]);
        op[i] = st;
    }
}

// ---------------- bucket build (g_cnt is zero on entry; see kAgg final) ----------------
__global__ void kFill(const int* __restrict__ src, const int* __restrict__ dst,
                      const int* __restrict__ et) {
    int i = blockIdx.x * blockDim.x + threadIdx.x;
    if (i >= NE) return;
    int d = dst[i];
    int pos = atomicAdd(&g_cnt[d], 1);
    if (pos < SLOTS) g_slot[d * SLOTS + pos] = src[i] | (et[i] << 18);
}

// ---------------- GEMM + score kernels ----------------
// layer 0: also acc = node_emb, and 2 tail blocks compute srel for both layers
__global__ __launch_bounds__(128)
void kG0(const float* __restrict__ node_emb, const float* __restrict__ W,
         const float* __restrict__ a, const float* __restrict__ W_r,
         const float* __restrict__ rel, float* __restrict__ acc) {
    __shared__ float Ws[DIMN * DIMN];
    __shared__ float a_s[DIMN], a_d[DIMN];
    __shared__ float v[DIMN];

    if (blockIdx.x >= GROW) {                 // srel tail blocks (layer 0/1)
        int l = blockIdx.x - GROW;
        int t = threadIdx.x;
        const float* Wr = W_r + (size_t)l * DIMN * DIMN;
        const float* ar = a + (size_t)l * 3 * DIMN + DIMN;
        if (t < DIMN) {
            float s = 0.f;
#pragma unroll
            for (int j = 0; j < DIMN; j++) s += Wr[t * DIMN + j] * ar[j];
            v[t] = s;
        }
        __syncthreads();
        if (t < NRELN) {
            const float* rl = rel + (size_t)l * NRELN * DIMN + (size_t)t * DIMN;
            float r = 0.f;
#pragma unroll
            for (int k = 0; k < DIMN; k++) r += rl[k] * v[k];
            g_srel[l * NRELN + t] = r;
        }
        return;
    }

    for (int i = threadIdx.x; i < DIMN * DIMN; i += 128) Ws[i] = W[i];
    if (threadIdx.x < DIMN) {
        a_s[threadIdx.x] = a[threadIdx.x];
        a_d[threadIdx.x] = a[2 * DIMN + threadIdx.x];
    }
    __syncthreads();

    int row = blockIdx.x * 128 + threadIdx.x;
    if (row >= NN) return;

    float4 xv[16];
    const float4* xp = (const float4*)(node_emb + (size_t)row * DIMN);
    float4* ap = (float4*)(acc + (size_t)row * DIMN);
#pragma unroll
    for (int j = 0; j < 16; j++) { xv[j] = xp[j]; ap[j] = xv[j]; }

    gemm_row(xv, Ws, a_s, a_d, row);
}

// layer 1: x from g_x
__global__ __launch_bounds__(128)
void kG1(const float* __restrict__ W, const float* __restrict__ a) {
    __shared__ float Ws[DIMN * DIMN];
    __shared__ float a_s[DIMN], a_d[DIMN];
    for (int i = threadIdx.x; i < DIMN * DIMN; i += 128) Ws[i] = W[i];
    if (threadIdx.x < DIMN) {
        a_s[threadIdx.x] = a[threadIdx.x];
        a_d[threadIdx.x] = a[2 * DIMN + threadIdx.x];
    }
    __syncthreads();

    int row = blockIdx.x * 128 + threadIdx.x;
    if (row >= NN) return;

    float4 xv[16];
    const float4* xp = (const float4*)(g_x + (size_t)row * DIMN);
#pragma unroll
    for (int j = 0; j < 16; j++) xv[j] = xp[j];

    gemm_row(xv, Ws, a_s, a_d, row);
}

// ---------------- gather aggregation: 4 nodes per warp, 8 lanes per node ----------
// Each lane owns 8 columns (one uint4 = 16B of fp16) of ITS node: one 128B line
// per edge, no inter-group combine shfls, epilogue with zero lane redundancy.
__global__ __launch_bounds__(256)
void kAgg(float* __restrict__ acc, int layer, int is_final) {
    __shared__ uint2 sh[8][4][SLOTS];       // [warp][group][slot] = {w, rowbase}

    int wid  = threadIdx.x >> 5;
    int lane = threadIdx.x & 31;
    int grp  = lane >> 3;                   // node group within warp (0-3)
    int c8   = lane & 7;                    // uint4 chunk (cols 8*c8 .. 8*c8+7)

    int n = blockIdx.x * 32 + wid * 4 + grp;
    if (n >= NN) return;

    int deg = g_cnt[n];
    deg = (deg > SLOTS) ? SLOTS : deg;
    float sdst_n = g_sdst[n];
    const float* srel_l = g_srel + layer * NRELN;
    const int* slot = g_slot + n * SLOTS;

    // stage 1: 8 lanes per node compute edge weights (full utilization at deg~8)
    float att = 0.f;
    for (int j = c8; j < deg; j += 8) {
        int p = slot[j];
        int s = p & 0x3FFFF;
        int et = p >> 18;
        float e = g_ssrc[s] + srel_l[et] + sdst_n;
        e = (e > 0.f) ? e : 0.2f * e;
        float w = __expf(e);
        sh[wid][grp][j] = make_uint2(__float_as_uint(w), (unsigned)s * 8u); // uint4 row base
        att += w;
    }
#pragma unroll
    for (int o = 1; o < 8; o <<= 1) att += __shfl_xor_sync(0xffffffffu, att, o);
    __syncwarp();

    // stage 2: serial over this node's edges; 8 lanes fetch one 128B line/edge
    float4 h0 = make_float4(0.f, 0.f, 0.f, 0.f);
    float4 h1 = make_float4(0.f, 0.f, 0.f, 0.f);
    const uint4* xh = (const uint4*)g_xth;
    const uint2* shg = sh[wid][grp];
#pragma unroll 2
    for (int j = 0; j < deg; j++) {
        uint2 t = shg[j];
        float w = __uint_as_float(t.x);
        uint4 u = __ldg(&xh[t.y + c8]);
        float2 a0 = __half22float2(*(const __half2*)&u.x);
        float2 a1 = __half22float2(*(const __half2*)&u.y);
        float2 a2 = __half22float2(*(const __half2*)&u.z);
        float2 a3 = __half22float2(*(const __half2*)&u.w);
        h0.x += w * a0.x; h0.y += w * a0.y; h0.z += w * a1.x; h0.w += w * a1.y;
        h1.x += w * a2.x; h1.y += w * a2.y; h1.z += w * a3.x; h1.w += w * a3.y;
    }

    float inv_s = 1.f / (att + 1e-10f);
    h0.x *= inv_s; h0.y *= inv_s; h0.z *= inv_s; h0.w *= inv_s;
    h1.x *= inv_s; h1.y *= inv_s; h1.z *= inv_s; h1.w *= inv_s;
    h0.x = (h0.x > 0.f) ? h0.x : __expf(h0.x) - 1.f;   // ELU
    h0.y = (h0.y > 0.f) ? h0.y : __expf(h0.y) - 1.f;
    h0.z = (h0.z > 0.f) ? h0.z : __expf(h0.z) - 1.f;
    h0.w = (h0.w > 0.f) ? h0.w : __expf(h0.w) - 1.f;
    h1.x = (h1.x > 0.f) ? h1.x : __expf(h1.x) - 1.f;
    h1.y = (h1.y > 0.f) ? h1.y : __expf(h1.y) - 1.f;
    h1.z = (h1.z > 0.f) ? h1.z : __expf(h1.z) - 1.f;
    h1.w = (h1.w > 0.f) ? h1.w : __expf(h1.w) - 1.f;

    float ss = h0.x * h0.x + h0.y * h0.y + h0.z * h0.z + h0.w * h0.w
             + h1.x * h1.x + h1.y * h1.y + h1.z * h1.z + h1.w * h1.w;
#pragma unroll
    for (int o = 1; o < 8; o <<= 1) ss += __shfl_xor_sync(0xffffffffu, ss, o);
    float inv = 1.f / fmaxf(sqrtf(ss), 1e-12f);
    h0.x *= inv; h0.y *= inv; h0.z *= inv; h0.w *= inv;
    h1.x *= inv; h1.y *= inv; h1.z *= inv; h1.w *= inv;

    float4* ap = (float4*)(acc + n * DIMN) + 2 * c8;   // each lane owns cols 8c8..8c8+7
    float4 a0 = ap[0], a1 = ap[1];
    if (is_final) {
        const float fs = 1.f / (float)(NLAY + 1);
        a0.x = (a0.x + h0.x) * fs; a0.y = (a0.y + h0.y) * fs;
        a0.z = (a0.z + h0.z) * fs; a0.w = (a0.w + h0.w) * fs;
        a1.x = (a1.x + h1.x) * fs; a1.y = (a1.y + h1.y) * fs;
        a1.z = (a1.z + h1.z) * fs; a1.w = (a1.w + h1.w) * fs;
        ap[0] = a0; ap[1] = a1;
        if (c8 == 0) g_cnt[n] = 0;          // leave counters zeroed for next run
    } else {
        a0.x += h0.x; a0.y += h0.y; a0.z += h0.z; a0.w += h0.w;
        a1.x += h1.x; a1.y += h1.y; a1.z += h1.z; a1.w += h1.w;
        ap[0] = a0; ap[1] = a1;
        float4* xp = (float4*)(g_x + n * DIMN) + 2 * c8;
        xp[0] = h0; xp[1] = h1;
    }
}

// ---------------- launch ----------------
extern "C" void kernel_launch(void* const* d_in, const int* in_sizes, int n_in,
                              void* d_out, int out_size) {
    const float* node_emb = (const float*)d_in[0];
    const float* W        = (const float*)d_in[1];   // [2,64,64]
    const float* W_r      = (const float*)d_in[2];   // [2,64,64]
    const float* a        = (const float*)d_in[3];   // [2,192]
    const float* rel      = (const float*)d_in[4];   // [2,32,64]
    const int*   eidx     = (const int*)d_in[5];     // [2, NE]
    const int*   etype    = (const int*)d_in[6];     // [NE]
    const int* src = eidx;
    const int* dst = eidx + NE;
    float* out = (float*)d_out;

    const int gAgg = (NN + 31) / 32;                 // 4688 blocks, 32 nodes each

    kFill<<<(NE + 255) / 256, 256>>>(src, dst, etype);
    kG0<<<GROW + 2, 128>>>(node_emb, W, a, W_r, rel, out);
    kAgg<<<gAgg, 256>>>(out, 0, 0);
    kG1<<<GROW, 128>>>(W + DIMN * DIMN, a + 3 * DIMN);
    kAgg<<<gAgg, 256>>>(out, 1, 1);
}

// round 16
// speedup vs baseline: 1.5348x; 1.2192x over previous
#include <cuda_runtime.h>
#include <cuda_fp16.h>
#include <math.h>

#define NN    150000
#define DIMN  64
#define NE    1200000
#define NRELN 32
#define NLAY  2
#define SLOTS 64
#define GB    1172                      // ceil(NN/128) GEMM blocks

// ---------------- scratch (device globals; no allocation allowed) ----------------
__device__ __half g_xth[NN * DIMN];     // xt = x @ W, fp16 (gather operand, 128B/row)
__device__ float  g_x[NN * DIMN];       // layer input x (post-epilogue), fp32
__device__ float  g_ssrc[NN];           // xt @ a_src
__device__ float  g_sdst[NN];           // xt @ a_dst
__device__ float  g_srel[NLAY * NRELN]; // rel @ (W_r @ a_rel), both layers
__device__ int    g_cnt[NN];            // per-dst degree (zero-init; kAgg-final re-zeroes)
__device__ int    g_slot[NN * SLOTS];   // per-dst packed (src | etype<<18)

// ---------------- bucket build (g_cnt is zero on entry; see kAgg final) ----------------
__global__ void kFill(const int* __restrict__ src, const int* __restrict__ dst,
                      const int* __restrict__ et) {
    int i = blockIdx.x * blockDim.x + threadIdx.x;
    if (i >= NE) return;
    int d = dst[i];
    int pos = atomicAdd(&g_cnt[d], 1);
    if (pos < SLOTS) g_slot[d * SLOTS + pos] = src[i] | (et[i] << 18);
}

// ---------------- tensor-core GEMM: xt = x @ W (fp16 HMMA, fp32 accum) -------------
// 128 rows/block, 256 threads (8 warps x 16 rows). Epilogue: xt->g_xth fp16,
// ssrc/sdst scores. is_l0: x from xin + acc=copy + 2 srel tail blocks.
__global__ __launch_bounds__(256)
void kGm(const float* __restrict__ xin, const float* __restrict__ W,
         const float* __restrict__ a_l, const float* __restrict__ W_r,
         const float* __restrict__ rel, float* __restrict__ acc, int is_l0) {
    __shared__ __align__(16) __half sW[64 * 64];    // swizzled [k][chunk]
    __shared__ __align__(16) __half sX[128 * 64];   // swizzled [row][chunk]; reused for xt
    __shared__ float sa[2 * DIMN];                  // a_src | a_dst
    __shared__ float v[DIMN];

    if (blockIdx.x >= GB) {                          // srel tail blocks (layer 0/1)
        int l = blockIdx.x - GB;
        int t = threadIdx.x;
        const float* Wr = W_r + (size_t)l * DIMN * DIMN;
        const float* ar = a_l - (size_t)0;           // note: a_l points at layer-0 'a'
        const float* arl = ar + (size_t)l * 3 * DIMN + DIMN;
        if (t < DIMN) {
            float s = 0.f;
#pragma unroll
            for (int j = 0; j < DIMN; j++) s += Wr[t * DIMN + j] * arl[j];
            v[t] = s;
        }
        __syncthreads();
        if (t < NRELN) {
            const float* rl = rel + (size_t)l * NRELN * DIMN + (size_t)t * DIMN;
            float r = 0.f;
#pragma unroll
            for (int k = 0; k < DIMN; k++) r += rl[k] * v[k];
            g_srel[l * NRELN + t] = r;
        }
        return;
    }

    int t = threadIdx.x;
    int rowbase = blockIdx.x * 128;
    const float* xsrc = is_l0 ? xin : g_x;

    // ---- load W (1024 float4) -> fp16 swizzled smem ----
#pragma unroll
    for (int j = 0; j < 4; j++) {
        int idx = t + j * 256;
        float4 w = ((const float4*)W)[idx];
        int k = idx >> 4, p = idx & 15;
        int chunk = p >> 1, hp = p & 1;
        int off = k * 64 + ((chunk ^ (k & 7)) << 3) + hp * 4;   // halves
        __half2 h0 = __floats2half2_rn(w.x, w.y);
        __half2 h1 = __floats2half2_rn(w.z, w.w);
        *(uint2*)(&sW[off]) = make_uint2(*(unsigned*)&h0, *(unsigned*)&h1);
    }
    // ---- load x tile (2048 float4) -> fp16 swizzled smem (+ acc copy for L0) ----
#pragma unroll
    for (int j = 0; j < 8; j++) {
        int idx = t + j * 256;
        int r = idx >> 4, p = idx & 15;
        int rg = rowbase + r;
        float4 x4 = make_float4(0.f, 0.f, 0.f, 0.f);
        if (rg < NN) {
            x4 = ((const float4*)xsrc)[(size_t)rg * 16 + p];
            if (is_l0) ((float4*)acc)[(size_t)rg * 16 + p] = x4;
        }
        int chunk = p >> 1, hp = p & 1;
        int off = r * 64 + ((chunk ^ (r & 7)) << 3) + hp * 4;
        __half2 h0 = __floats2half2_rn(x4.x, x4.y);
        __half2 h1 = __floats2half2_rn(x4.z, x4.w);
        *(uint2*)(&sX[off]) = make_uint2(*(unsigned*)&h0, *(unsigned*)&h1);
    }
    if (t < 2 * DIMN) sa[t] = (t < DIMN) ? a_l[t] : a_l[DIMN + t];  // a_src | a_dst (a[2D..3D))
    __syncthreads();

    unsigned sxa = (unsigned)__cvta_generic_to_shared(sX);
    unsigned swa = (unsigned)__cvta_generic_to_shared(sW);

    int warp = t >> 5, l = t & 31;
    int m0 = warp * 16;

    // ---- A fragments: 4 k-tiles, ldmatrix.x4 each ----
    unsigned A[4][4];
    {
        int tile = l >> 3;
        int r_loc = m0 + ((tile & 1) << 3) + (l & 7);
#pragma unroll
        for (int kt = 0; kt < 4; kt++) {
            int kchunk = 2 * kt + (tile >> 1);
            unsigned addr = sxa + (unsigned)(r_loc * 128 + ((kchunk ^ (r_loc & 7)) << 4));
            asm volatile("ldmatrix.sync.aligned.m8n8.x4.shared.b16 {%0,%1,%2,%3}, [%4];"
                         : "=r"(A[kt][0]), "=r"(A[kt][1]), "=r"(A[kt][2]), "=r"(A[kt][3])
                         : "r"(addr));
        }
    }

    // ---- mma loop ----
    float C[8][4];
#pragma unroll
    for (int nt = 0; nt < 8; nt++)
#pragma unroll
        for (int q = 0; q < 4; q++) C[nt][q] = 0.f;

    int ll = l & 15;
    unsigned boff = ((unsigned)(ll & 7)) ;            // for chunk xor
#pragma unroll
    for (int kt = 0; kt < 4; kt++) {
        unsigned brow = swa + (unsigned)((kt * 16 + ll) * 128);
#pragma unroll
        for (int nt = 0; nt < 8; nt++) {
            unsigned addr = brow + (unsigned)(((nt ^ (int)boff) << 4));
            unsigned b0, b1;
            asm volatile("ldmatrix.sync.aligned.m8n8.x2.trans.shared.b16 {%0,%1}, [%2];"
                         : "=r"(b0), "=r"(b1) : "r"(addr));
            asm volatile("mma.sync.aligned.m16n8k16.row.col.f32.f16.f16.f32 "
                         "{%0,%1,%2,%3}, {%4,%5,%6,%7}, {%8,%9}, {%0,%1,%2,%3};"
                         : "+f"(C[nt][0]), "+f"(C[nt][1]), "+f"(C[nt][2]), "+f"(C[nt][3])
                         : "r"(A[kt][0]), "r"(A[kt][1]), "r"(A[kt][2]), "r"(A[kt][3]),
                           "r"(b0), "r"(b1));
        }
    }

    // ---- write C back to sX (own warp's rows; fp16 swizzled) ----
    {
        int g = l >> 2, tq = l & 3;
        int ra = m0 + g, rb = ra + 8;
        char* sxb = (char*)sX;
#pragma unroll
        for (int nt = 0; nt < 8; nt++) {
            *(half2*)(sxb + ra * 128 + ((nt ^ (ra & 7)) << 4) + tq * 4) =
                __floats2half2_rn(C[nt][0], C[nt][1]);
            *(half2*)(sxb + rb * 128 + ((nt ^ (rb & 7)) << 4) + tq * 4) =
                __floats2half2_rn(C[nt][2], C[nt][3]);
        }
    }
    __syncthreads();

    // ---- epilogue: xt -> g_xth (coalesced uint4), scores ssrc/sdst ----
    {
        int r = t >> 1, h = t & 1;
        int rg = rowbase + r;
        if (rg >= NN) return;
        char* sxb = (char*)sX;
        float ssp = 0.f, sdp = 0.f;
#pragma unroll
        for (int j = 0; j < 4; j++) {
            int c = h * 4 + j;
            uint4 u = *(uint4*)(sxb + r * 128 + ((c ^ (r & 7)) << 4));
            ((uint4*)g_xth)[(size_t)rg * 8 + c] = u;
            float2 f0 = __half22float2(*(const __half2*)&u.x);
            float2 f1 = __half22float2(*(const __half2*)&u.y);
            float2 f2 = __half22float2(*(const __half2*)&u.z);
            float2 f3 = __half22float2(*(const __half2*)&u.w);
            const float* as = sa + c * 8;
            const float* ad = sa + DIMN + c * 8;
            ssp += f0.x * as[0] + f0.y * as[1] + f1.x * as[2] + f1.y * as[3]
                 + f2.x * as[4] + f2.y * as[5] + f3.x * as[6] + f3.y * as[7];
            sdp += f0.x * ad[0] + f0.y * ad[1] + f1.x * ad[2] + f1.y * ad[3]
                 + f2.x * ad[4] + f2.y * ad[5] + f3.x * ad[6] + f3.y * ad[7];
        }
        float sst = ssp + __shfl_xor_sync(0xffffffffu, ssp, 1);
        float sdt = sdp + __shfl_xor_sync(0xffffffffu, sdp, 1);
        if (h == 0) g_ssrc[rg] = sst;
        else        g_sdst[rg] = sdt;
    }
}

// ---------------- gather aggregation: 4 nodes per warp, 8 lanes per node ----------
__global__ __launch_bounds__(256)
void kAgg(float* __restrict__ acc, int layer, int is_final) {
    __shared__ uint2 sh[8][4][SLOTS];       // [warp][group][slot] = {w, rowbase}

    int wid  = threadIdx.x >> 5;
    int lane = threadIdx.x & 31;
    int grp  = lane >> 3;                   // node group within warp (0-3)
    int c8   = lane & 7;                    // uint4 chunk (cols 8*c8 .. 8*c8+7)

    int n = blockIdx.x * 32 + wid * 4 + grp;
    if (n >= NN) return;

    int deg = g_cnt[n];
    deg = (deg > SLOTS) ? SLOTS : deg;
    float sdst_n = g_sdst[n];
    const float* srel_l = g_srel + layer * NRELN;
    const int* slot = g_slot + n * SLOTS;

    // stage 1: 8 lanes per node compute edge weights
    float att = 0.f;
    for (int j = c8; j < deg; j += 8) {
        int p = slot[j];
        int s = p & 0x3FFFF;
        int et = p >> 18;
        float e = g_ssrc[s] + srel_l[et] + sdst_n;
        e = (e > 0.f) ? e : 0.2f * e;
        float w = __expf(e);
        sh[wid][grp][j] = make_uint2(__float_as_uint(w), (unsigned)s * 8u);
        att += w;
    }
#pragma unroll
    for (int o = 1; o < 8; o <<= 1) att += __shfl_xor_sync(0xffffffffu, att, o);
    __syncwarp();

    // stage 2: serial over this node's edges; 8 lanes fetch one 128B line/edge
    float4 h0 = make_float4(0.f, 0.f, 0.f, 0.f);
    float4 h1 = make_float4(0.f, 0.f, 0.f, 0.f);
    const uint4* xh = (const uint4*)g_xth;
    const uint2* shg = sh[wid][grp];
#pragma unroll 2
    for (int j = 0; j < deg; j++) {
        uint2 tt = shg[j];
        float w = __uint_as_float(tt.x);
        uint4 u = __ldg(&xh[tt.y + c8]);
        float2 a0 = __half22float2(*(const __half2*)&u.x);
        float2 a1 = __half22float2(*(const __half2*)&u.y);
        float2 a2 = __half22float2(*(const __half2*)&u.z);
        float2 a3 = __half22float2(*(const __half2*)&u.w);
        h0.x += w * a0.x; h0.y += w * a0.y; h0.z += w * a1.x; h0.w += w * a1.y;
        h1.x += w * a2.x; h1.y += w * a2.y; h1.z += w * a3.x; h1.w += w * a3.y;
    }

    float inv_s = 1.f / (att + 1e-10f);
    h0.x *= inv_s; h0.y *= inv_s; h0.z *= inv_s; h0.w *= inv_s;
    h1.x *= inv_s; h1.y *= inv_s; h1.z *= inv_s; h1.w *= inv_s;
    h0.x = (h0.x > 0.f) ? h0.x : __expf(h0.x) - 1.f;   // ELU
    h0.y = (h0.y > 0.f) ? h0.y : __expf(h0.y) - 1.f;
    h0.z = (h0.z > 0.f) ? h0.z : __expf(h0.z) - 1.f;
    h0.w = (h0.w > 0.f) ? h0.w : __expf(h0.w) - 1.f;
    h1.x = (h1.x > 0.f) ? h1.x : __expf(h1.x) - 1.f;
    h1.y = (h1.y > 0.f) ? h1.y : __expf(h1.y) - 1.f;
    h1.z = (h1.z > 0.f) ? h1.z : __expf(h1.z) - 1.f;
    h1.w = (h1.w > 0.f) ? h1.w : __expf(h1.w) - 1.f;

    float ss = h0.x * h0.x + h0.y * h0.y + h0.z * h0.z + h0.w * h0.w
             + h1.x * h1.x + h1.y * h1.y + h1.z * h1.z + h1.w * h1.w;
#pragma unroll
    for (int o = 1; o < 8; o <<= 1) ss += __shfl_xor_sync(0xffffffffu, ss, o);
    float inv = 1.f / fmaxf(sqrtf(ss), 1e-12f);
    h0.x *= inv; h0.y *= inv; h0.z *= inv; h0.w *= inv;
    h1.x *= inv; h1.y *= inv; h1.z *= inv; h1.w *= inv;

    float4* ap = (float4*)(acc + n * DIMN) + 2 * c8;
    float4 a0 = ap[0], a1 = ap[1];
    if (is_final) {
        const float fs = 1.f / (float)(NLAY + 1);
        a0.x = (a0.x + h0.x) * fs; a0.y = (a0.y + h0.y) * fs;
        a0.z = (a0.z + h0.z) * fs; a0.w = (a0.w + h0.w) * fs;
        a1.x = (a1.x + h1.x) * fs; a1.y = (a1.y + h1.y) * fs;
        a1.z = (a1.z + h1.z) * fs; a1.w = (a1.w + h1.w) * fs;
        ap[0] = a0; ap[1] = a1;
        if (c8 == 0) g_cnt[n] = 0;          // leave counters zeroed for next run
    } else {
        a0.x += h0.x; a0.y += h0.y; a0.z += h0.z; a0.w += h0.w;
        a1.x += h1.x; a1.y += h1.y; a1.z += h1.z; a1.w += h1.w;
        ap[0] = a0; ap[1] = a1;
        float4* xp = (float4*)(g_x + n * DIMN) + 2 * c8;
        xp[0] = h0; xp[1] = h1;
    }
}

// ---------------- launch ----------------
extern "C" void kernel_launch(void* const* d_in, const int* in_sizes, int n_in,
                              void* d_out, int out_size) {
    const float* node_emb = (const float*)d_in[0];
    const float* W        = (const float*)d_in[1];   // [2,64,64]
    const float* W_r      = (const float*)d_in[2];   // [2,64,64]
    const float* a        = (const float*)d_in[3];   // [2,192]
    const float* rel      = (const float*)d_in[4];   // [2,32,64]
    const int*   eidx     = (const int*)d_in[5];     // [2, NE]
    const int*   etype    = (const int*)d_in[6];     // [NE]
    const int* src = eidx;
    const int* dst = eidx + NE;
    float* out = (float*)d_out;

    const int gAgg = (NN + 31) / 32;

    kFill<<<(NE + 255) / 256, 256>>>(src, dst, etype);
    kGm<<<GB + 2, 256>>>(node_emb, W, a, W_r, rel, out, 1);
    kAgg<<<gAgg, 256>>>(out, 0, 0);
    kGm<<<GB, 256>>>(nullptr, W + DIMN * DIMN, a + 3 * DIMN, W_r, rel, out, 0);
    kAgg<<<gAgg, 256>>>(out, 1, 1);
}

// round 17
// speedup vs baseline: 2.2859x; 1.4894x over previous
#include <cuda_runtime.h>
#include <cuda_fp16.h>
#include <math.h>

#define NN    150000
#define DIMN  64
#define NE    1200000
#define NRELN 32
#define NLAY  2
#define SLOTS 64
#define GB    1172                      // ceil(NN/128) GEMM blocks
#define FB    4688                      // ceil(NE/256) fill blocks

// ---------------- scratch (device globals; no allocation allowed) ----------------
__device__ __half g_xth[NN * DIMN];     // xt = x @ W, fp16 (gather operand, 128B/row)
__device__ __half g_xh[NN * DIMN];      // layer input x, fp16 (fed to HMMA anyway)
__device__ float  g_ssrc[NN];           // xt @ a_src
__device__ float  g_sdst[NN];           // xt @ a_dst
__device__ float  g_srel[NLAY * NRELN]; // rel @ (W_r @ a_rel), both layers
__device__ int    g_cnt[NN];            // per-dst degree (zero-init; kAgg-final re-zeroes)
__device__ int    g_slot[NN * SLOTS];   // per-dst packed (src | etype<<18)

// ---------------- packed f32x2 helpers ----------------
__device__ __forceinline__ unsigned long long pack2(float lo, float hi) {
    unsigned long long r;
    asm("mov.b64 %0, {%1,%2};" : "=l"(r) : "f"(lo), "f"(hi));
    return r;
}
__device__ __forceinline__ void ffma2(unsigned long long& d,
                                      unsigned long long a, unsigned long long b) {
    asm("fma.rn.f32x2 %0, %1, %2, %3;" : "=l"(d) : "l"(a), "l"(b), "l"(d));
}
__device__ __forceinline__ float2 unpack2(unsigned long long v) {
    float2 f;
    asm("mov.b64 {%0,%1}, %2;" : "=f"(f.x), "=f"(f.y) : "l"(v));
    return f;
}

// ---------------- tensor-core GEMM: xt = x @ W (fp16 HMMA, fp32 accum) -------------
// Blocks [0,GB): GEMM 128 rows each. Blocks [GB,GB+2): srel (l0 only).
// Blocks [GB+2,...): edge bucket fill (l0 only) — overlapped work, no extra launch.
__global__ __launch_bounds__(256)
void kGm(const float* __restrict__ xin, const float* __restrict__ W,
         const float* __restrict__ a_l, const float* __restrict__ W_r,
         const float* __restrict__ rel, float* __restrict__ acc,
         const int* __restrict__ src, const int* __restrict__ dst,
         const int* __restrict__ et, int is_l0) {
    __shared__ __align__(16) __half sW[64 * 64];    // swizzled [k][chunk]
    __shared__ __align__(16) __half sX[128 * 64];   // swizzled [row][chunk]; reused for xt
    __shared__ float sa[2 * DIMN];                  // a_src | a_dst
    __shared__ float v[DIMN];

    if (blockIdx.x >= GB + 2) {                      // fill blocks (l0 launch only)
        int i = (blockIdx.x - GB - 2) * 256 + threadIdx.x;
        if (i >= NE) return;
        int d = dst[i];
        int pos = atomicAdd(&g_cnt[d], 1);
        if (pos < SLOTS) g_slot[d * SLOTS + pos] = src[i] | (et[i] << 18);
        return;
    }
    if (blockIdx.x >= GB) {                          // srel tail blocks (layer 0/1)
        int l = blockIdx.x - GB;
        int t = threadIdx.x;
        const float* Wr = W_r + (size_t)l * DIMN * DIMN;
        const float* arl = a_l + (size_t)l * 3 * DIMN + DIMN;
        if (t < DIMN) {
            float s = 0.f;
#pragma unroll
            for (int j = 0; j < DIMN; j++) s += Wr[t * DIMN + j] * arl[j];
            v[t] = s;
        }
        __syncthreads();
        if (t < NRELN) {
            const float* rl = rel + (size_t)l * NRELN * DIMN + (size_t)t * DIMN;
            float r = 0.f;
#pragma unroll
            for (int k = 0; k < DIMN; k++) r += rl[k] * v[k];
            g_srel[l * NRELN + t] = r;
        }
        return;
    }

    int t = threadIdx.x;
    int rowbase = blockIdx.x * 128;

    // ---- load W (1024 float4) -> fp16 swizzled smem ----
#pragma unroll
    for (int j = 0; j < 4; j++) {
        int idx = t + j * 256;
        float4 w = ((const float4*)W)[idx];
        int k = idx >> 4, p = idx & 15;
        int chunk = p >> 1, hp = p & 1;
        int off = k * 64 + ((chunk ^ (k & 7)) << 3) + hp * 4;   // halves
        __half2 h0 = __floats2half2_rn(w.x, w.y);
        __half2 h1 = __floats2half2_rn(w.z, w.w);
        *(uint2*)(&sW[off]) = make_uint2(*(unsigned*)&h0, *(unsigned*)&h1);
    }
    // ---- load x tile -> fp16 swizzled smem ----
    if (is_l0) {
        // fp32 source, convert; also acc = copy
#pragma unroll
        for (int j = 0; j < 8; j++) {
            int idx = t + j * 256;
            int r = idx >> 4, p = idx & 15;
            int rg = rowbase + r;
            float4 x4 = make_float4(0.f, 0.f, 0.f, 0.f);
            if (rg < NN) {
                x4 = ((const float4*)xin)[(size_t)rg * 16 + p];
                ((float4*)acc)[(size_t)rg * 16 + p] = x4;
            }
            int chunk = p >> 1, hp = p & 1;
            int off = r * 64 + ((chunk ^ (r & 7)) << 3) + hp * 4;
            __half2 h0 = __floats2half2_rn(x4.x, x4.y);
            __half2 h1 = __floats2half2_rn(x4.z, x4.w);
            *(uint2*)(&sX[off]) = make_uint2(*(unsigned*)&h0, *(unsigned*)&h1);
        }
    } else {
        // fp16 source: straight uint4 copies (1024 of them)
#pragma unroll
        for (int j = 0; j < 4; j++) {
            int idx = t + j * 256;
            int r = idx >> 3, c = idx & 7;
            int rg = rowbase + r;
            uint4 u = make_uint4(0u, 0u, 0u, 0u);
            if (rg < NN) u = ((const uint4*)g_xh)[(size_t)rg * 8 + c];
            int off = r * 64 + ((c ^ (r & 7)) << 3);
            *(uint4*)(&sX[off]) = u;
        }
    }
    if (t < 2 * DIMN) sa[t] = (t < DIMN) ? a_l[t] : a_l[DIMN + t];  // a_src | a_dst
    __syncthreads();

    unsigned sxa = (unsigned)__cvta_generic_to_shared(sX);
    unsigned swa = (unsigned)__cvta_generic_to_shared(sW);

    int warp = t >> 5, l = t & 31;
    int m0 = warp * 16;

    // ---- A fragments: 4 k-tiles, ldmatrix.x4 each ----
    unsigned A[4][4];
    {
        int tile = l >> 3;
        int r_loc = m0 + ((tile & 1) << 3) + (l & 7);
#pragma unroll
        for (int kt = 0; kt < 4; kt++) {
            int kchunk = 2 * kt + (tile >> 1);
            unsigned addr = sxa + (unsigned)(r_loc * 128 + ((kchunk ^ (r_loc & 7)) << 4));
            asm volatile("ldmatrix.sync.aligned.m8n8.x4.shared.b16 {%0,%1,%2,%3}, [%4];"
                         : "=r"(A[kt][0]), "=r"(A[kt][1]), "=r"(A[kt][2]), "=r"(A[kt][3])
                         : "r"(addr));
        }
    }

    // ---- mma loop ----
    float C[8][4];
#pragma unroll
    for (int nt = 0; nt < 8; nt++)
#pragma unroll
        for (int q = 0; q < 4; q++) C[nt][q] = 0.f;

    int ll = l & 15;
    unsigned boff = (unsigned)(ll & 7);
#pragma unroll
    for (int kt = 0; kt < 4; kt++) {
        unsigned brow = swa + (unsigned)((kt * 16 + ll) * 128);
#pragma unroll
        for (int nt = 0; nt < 8; nt++) {
            unsigned addr = brow + (unsigned)(((nt ^ (int)boff) << 4));
            unsigned b0, b1;
            asm volatile("ldmatrix.sync.aligned.m8n8.x2.trans.shared.b16 {%0,%1}, [%2];"
                         : "=r"(b0), "=r"(b1) : "r"(addr));
            asm volatile("mma.sync.aligned.m16n8k16.row.col.f32.f16.f16.f32 "
                         "{%0,%1,%2,%3}, {%4,%5,%6,%7}, {%8,%9}, {%0,%1,%2,%3};"
                         : "+f"(C[nt][0]), "+f"(C[nt][1]), "+f"(C[nt][2]), "+f"(C[nt][3])
                         : "r"(A[kt][0]), "r"(A[kt][1]), "r"(A[kt][2]), "r"(A[kt][3]),
                           "r"(b0), "r"(b1));
        }
    }

    // ---- write C back to sX (own warp's rows; fp16 swizzled) ----
    {
        int g = l >> 2, tq = l & 3;
        int ra = m0 + g, rb = ra + 8;
        char* sxb = (char*)sX;
#pragma unroll
        for (int nt = 0; nt < 8; nt++) {
            *(half2*)(sxb + ra * 128 + ((nt ^ (ra & 7)) << 4) + tq * 4) =
                __floats2half2_rn(C[nt][0], C[nt][1]);
            *(half2*)(sxb + rb * 128 + ((nt ^ (rb & 7)) << 4) + tq * 4) =
                __floats2half2_rn(C[nt][2], C[nt][3]);
        }
    }
    __syncthreads();

    // ---- epilogue: xt -> g_xth (coalesced uint4), scores ssrc/sdst ----
    {
        int r = t >> 1, h = t & 1;
        int rg = rowbase + r;
        if (rg >= NN) return;
        char* sxb = (char*)sX;
        float ssp = 0.f, sdp = 0.f;
#pragma unroll
        for (int j = 0; j < 4; j++) {
            int c = h * 4 + j;
            uint4 u = *(uint4*)(sxb + r * 128 + ((c ^ (r & 7)) << 4));
            ((uint4*)g_xth)[(size_t)rg * 8 + c] = u;
            float2 f0 = __half22float2(*(const __half2*)&u.x);
            float2 f1 = __half22float2(*(const __half2*)&u.y);
            float2 f2 = __half22float2(*(const __half2*)&u.z);
            float2 f3 = __half22float2(*(const __half2*)&u.w);
            const float* as = sa + c * 8;
            const float* ad = sa + DIMN + c * 8;
            ssp += f0.x * as[0] + f0.y * as[1] + f1.x * as[2] + f1.y * as[3]
                 + f2.x * as[4] + f2.y * as[5] + f3.x * as[6] + f3.y * as[7];
            sdp += f0.x * ad[0] + f0.y * ad[1] + f1.x * ad[2] + f1.y * ad[3]
                 + f2.x * ad[4] + f2.y * ad[5] + f3.x * ad[6] + f3.y * ad[7];
        }
        float sst = ssp + __shfl_xor_sync(0xffffffffu, ssp, 1);
        float sdt = sdp + __shfl_xor_sync(0xffffffffu, sdp, 1);
        if (h == 0) g_ssrc[rg] = sst;
        else        g_sdst[rg] = sdt;
    }
}

// ---------------- gather aggregation: 4 nodes per warp, 8 lanes per node ----------
// Stage 2 accumulates with packed fma.rn.f32x2 (4 FFMA2/edge-lane instead of 8 FFMA).
__global__ __launch_bounds__(256)
void kAgg(float* __restrict__ acc, int layer, int is_final) {
    __shared__ uint2 sh[8][4][SLOTS];       // [warp][group][slot] = {w, rowbase}

    int wid  = threadIdx.x >> 5;
    int lane = threadIdx.x & 31;
    int grp  = lane >> 3;                   // node group within warp (0-3)
    int c8   = lane & 7;                    // uint4 chunk (cols 8*c8 .. 8*c8+7)

    int n = blockIdx.x * 32 + wid * 4 + grp;
    if (n >= NN) return;

    int deg = g_cnt[n];
    deg = (deg > SLOTS) ? SLOTS : deg;
    float sdst_n = g_sdst[n];
    const float* srel_l = g_srel + layer * NRELN;
    const int* slot = g_slot + n * SLOTS;

    // stage 1: 8 lanes per node compute edge weights
    float att = 0.f;
    for (int j = c8; j < deg; j += 8) {
        int p = slot[j];
        int s = p & 0x3FFFF;
        int et = p >> 18;
        float e = g_ssrc[s] + srel_l[et] + sdst_n;
        e = (e > 0.f) ? e : 0.2f * e;
        float w = __expf(e);
        sh[wid][grp][j] = make_uint2(__float_as_uint(w), (unsigned)s * 8u);
        att += w;
    }
#pragma unroll
    for (int o = 1; o < 8; o <<= 1) att += __shfl_xor_sync(0xffffffffu, att, o);
    __syncwarp();

    // stage 2: serial over this node's edges; 8 lanes fetch one 128B line/edge
    unsigned long long acc2[4] = {0ull, 0ull, 0ull, 0ull};
    const uint4* xh = (const uint4*)g_xth;
    const uint2* shg = sh[wid][grp];
#pragma unroll 2
    for (int j = 0; j < deg; j++) {
        uint2 tt = shg[j];
        float w = __uint_as_float(tt.x);
        unsigned long long w2 = pack2(w, w);
        uint4 u = __ldg(&xh[tt.y + c8]);
        float2 f0 = __half22float2(*(const __half2*)&u.x);
        float2 f1 = __half22float2(*(const __half2*)&u.y);
        float2 f2 = __half22float2(*(const __half2*)&u.z);
        float2 f3 = __half22float2(*(const __half2*)&u.w);
        ffma2(acc2[0], pack2(f0.x, f0.y), w2);
        ffma2(acc2[1], pack2(f1.x, f1.y), w2);
        ffma2(acc2[2], pack2(f2.x, f2.y), w2);
        ffma2(acc2[3], pack2(f3.x, f3.y), w2);
    }
    float2 p0 = unpack2(acc2[0]), p1 = unpack2(acc2[1]);
    float2 p2 = unpack2(acc2[2]), p3 = unpack2(acc2[3]);
    float4 h0 = make_float4(p0.x, p0.y, p1.x, p1.y);
    float4 h1 = make_float4(p2.x, p2.y, p3.x, p3.y);

    float inv_s = 1.f / (att + 1e-10f);
    h0.x *= inv_s; h0.y *= inv_s; h0.z *= inv_s; h0.w *= inv_s;
    h1.x *= inv_s; h1.y *= inv_s; h1.z *= inv_s; h1.w *= inv_s;
    h0.x = (h0.x > 0.f) ? h0.x : __expf(h0.x) - 1.f;   // ELU
    h0.y = (h0.y > 0.f) ? h0.y : __expf(h0.y) - 1.f;
    h0.z = (h0.z > 0.f) ? h0.z : __expf(h0.z) - 1.f;
    h0.w = (h0.w > 0.f) ? h0.w : __expf(h0.w) - 1.f;
    h1.x = (h1.x > 0.f) ? h1.x : __expf(h1.x) - 1.f;
    h1.y = (h1.y > 0.f) ? h1.y : __expf(h1.y) - 1.f;
    h1.z = (h1.z > 0.f) ? h1.z : __expf(h1.z) - 1.f;
    h1.w = (h1.w > 0.f) ? h1.w : __expf(h1.w) - 1.f;

    float ss = h0.x * h0.x + h0.y * h0.y + h0.z * h0.z + h0.w * h0.w
             + h1.x * h1.x + h1.y * h1.y + h1.z * h1.z + h1.w * h1.w;
#pragma unroll
    for (int o = 1; o < 8; o <<= 1) ss += __shfl_xor_sync(0xffffffffu, ss, o);
    float inv = 1.f / fmaxf(sqrtf(ss), 1e-12f);
    h0.x *= inv; h0.y *= inv; h0.z *= inv; h0.w *= inv;
    h1.x *= inv; h1.y *= inv; h1.z *= inv; h1.w *= inv;

    float4* ap = (float4*)(acc + n * DIMN) + 2 * c8;
    float4 a0 = ap[0], a1 = ap[1];
    if (is_final) {
        const float fs = 1.f / (float)(NLAY + 1);
        a0.x = (a0.x + h0.x) * fs; a0.y = (a0.y + h0.y) * fs;
        a0.z = (a0.z + h0.z) * fs; a0.w = (a0.w + h0.w) * fs;
        a1.x = (a1.x + h1.x) * fs; a1.y = (a1.y + h1.y) * fs;
        a1.z = (a1.z + h1.z) * fs; a1.w = (a1.w + h1.w) * fs;
        ap[0] = a0; ap[1] = a1;
        if (c8 == 0) g_cnt[n] = 0;          // leave counters zeroed for next run
    } else {
        a0.x += h0.x; a0.y += h0.y; a0.z += h0.z; a0.w += h0.w;
        a1.x += h1.x; a1.y += h1.y; a1.z += h1.z; a1.w += h1.w;
        ap[0] = a0; ap[1] = a1;
        // store x in fp16 — the GEMM converts to fp16 anyway, so this is precision-free
        uint4 o;
        __half2 q0 = __floats2half2_rn(h0.x, h0.y);
        __half2 q1 = __floats2half2_rn(h0.z, h0.w);
        __half2 q2 = __floats2half2_rn(h1.x, h1.y);
        __half2 q3 = __floats2half2_rn(h1.z, h1.w);
        o.x = *(unsigned*)&q0; o.y = *(unsigned*)&q1;
        o.z = *(unsigned*)&q2; o.w = *(unsigned*)&q3;
        ((uint4*)g_xh)[(size_t)n * 8 + c8] = o;
    }
}

// ---------------- launch ----------------
extern "C" void kernel_launch(void* const* d_in, const int* in_sizes, int n_in,
                              void* d_out, int out_size) {
    const float* node_emb = (const float*)d_in[0];
    const float* W        = (const float*)d_in[1];   // [2,64,64]
    const float* W_r      = (const float*)d_in[2];   // [2,64,64]
    const float* a        = (const float*)d_in[3];   // [2,192]
    const float* rel      = (const float*)d_in[4];   // [2,32,64]
    const int*   eidx     = (const int*)d_in[5];     // [2, NE]
    const int*   etype    = (const int*)d_in[6];     // [NE]
    const int* src = eidx;
    const int* dst = eidx + NE;
    float* out = (float*)d_out;

    const int gAgg = (NN + 31) / 32;

    // l0 launch carries GEMM + srel + edge-bucket fill blocks (overlapped)
    kGm<<<GB + 2 + FB, 256>>>(node_emb, W, a, W_r, rel, out, src, dst, etype, 1);
    kAgg<<<gAgg, 256>>>(out, 0, 0);
    kGm<<<GB, 256>>>(nullptr, W + DIMN * DIMN, a + 3 * DIMN, W_r, rel, out,
                     src, dst, etype, 0);
    kAgg<<<gAgg, 256>>>(out, 1, 1);
}